// round 15
// baseline (speedup 1.0000x reference)
#include <cuda_runtime.h>

// MemoryModule: B=8,L=12,T=36,D=1024,F=3,C=32
// v15: k_out on tensor cores — mma.sync.m16n8k8.tf32 with 3xTF32 split
//      (hi*hi + hi*lo + lo*hi) for fp32-grade accuracy. k_score emits tf32
//      hi/lo planes of att. k_gram unchanged (R12 variant).

#define Bb 8
#define Ll 12
#define Tt 36
#define Dd 1024
#define Ff 3
#define Cc 32
#define BL (Bb * Ll)
#define DF (Dd * Ff)        // 3072
#define DC 64
#define CHUNKS (Dd / DC)    // 16
#define NCOL (DC * Ff)      // 192 columns per chunk
#define BSTR 196            // padded B row stride (196 mod 32 = 4 -> conflict-free)

__device__ __align__(16) float g_G[4 * BL * Tt * 12];
__device__ __align__(16) float g_XL[4][BL][4];
// att tf32 planes: [bl][hi/lo][t 36][c 36(pad)]
__device__ __align__(16) float g_atts[BL * 2 * Tt * 36];

#define CP16(dst, src) \
    asm volatile("cp.async.cg.shared.global [%0], [%1], 16;" :: "r"(dst), "l"(src))

__device__ __forceinline__ unsigned tf32_rna(float x) {
    unsigned r;
    asm("cvt.rna.tf32.f32 %0, %1;" : "=r"(r) : "f"(x));
    return r;
}

#define MMA_TF32(c, a, b0, b1) \
    asm("mma.sync.aligned.m16n8k8.row.col.f32.tf32.tf32.f32 " \
        "{%0,%1,%2,%3}, {%4,%5,%6,%7}, {%8,%9}, {%0,%1,%2,%3};" \
        : "+f"((c)[0]), "+f"((c)[1]), "+f"((c)[2]), "+f"((c)[3]) \
        : "r"((a)[0]), "r"((a)[1]), "r"((a)[2]), "r"((a)[3]), \
          "r"(b0), "r"(b1))

// ---------------------------------------------------------------------------
// k_gram: R12/R10 variant verbatim. Grid (18,96) x 128.
// ---------------------------------------------------------------------------
#define SEG_F 768
#define WARP_SMEM (3 * SEG_F)

template <bool AXL>
__device__ __forceinline__ void gram_task(
    const float* __restrict__ xp, const float* __restrict__ lp,
    int lane, int bl, int t, int slot)
{
    float V[12];
    #pragma unroll
    for (int j = 0; j < 12; j++) V[j] = 0.0f;
    float X0 = 0.0f, X1 = 0.0f, X2 = 0.0f;

    #pragma unroll
    for (int it = 0; it < 8; it++) {
        int o = it * 96 + lane * 3;
        float a0 = xp[o + 0], a1 = xp[o + 1], a2 = xp[o + 2];
        float b0 = lp[o + 0], b1 = lp[o + 1], b2 = lp[o + 2];
        V[0] = fmaf(a0, b0, V[0]); V[1] = fmaf(a0, b1, V[1]); V[2] = fmaf(a0, b2, V[2]);
        V[3] = fmaf(a1, b0, V[3]); V[4] = fmaf(a1, b1, V[4]); V[5] = fmaf(a1, b2, V[5]);
        V[6] = fmaf(a2, b0, V[6]); V[7] = fmaf(a2, b1, V[7]); V[8] = fmaf(a2, b2, V[8]);
        V[9] += a0; V[10] += a1; V[11] += a2;
        if (AXL) { X0 += b0; X1 += b1; X2 += b2; }
    }

    #pragma unroll
    for (int j = 0; j < 12; j++) {
        #pragma unroll
        for (int o = 16; o; o >>= 1) V[j] += __shfl_down_sync(~0u, V[j], o);
    }
    if (AXL) {
        #pragma unroll
        for (int o = 16; o; o >>= 1) {
            X0 += __shfl_down_sync(~0u, X0, o);
            X1 += __shfl_down_sync(~0u, X1, o);
            X2 += __shfl_down_sync(~0u, X2, o);
        }
    }
    if (lane == 0) {
        float* gp = g_G + (((size_t)slot * BL + bl) * Tt + t) * 12;
        *(float4*)(gp + 0) = make_float4(V[0], V[1], V[2], V[3]);
        *(float4*)(gp + 4) = make_float4(V[4], V[5], V[6], V[7]);
        *(float4*)(gp + 8) = make_float4(V[8], V[9], V[10], V[11]);
        if (AXL) {
            g_XL[slot][bl][0] = X0;
            g_XL[slot][bl][1] = X1;
            g_XL[slot][bl][2] = X2;
        }
    }
}

__global__ __launch_bounds__(128) void k_gram(
    const float* __restrict__ xh_g, const float* __restrict__ xl_g)
{
    extern __shared__ float sg[];

    int bx = blockIdx.x, bl = blockIdx.y;
    int tg = bx % 9, dh = bx / 9;
    int tid = threadIdx.x, w = tid >> 5, lane = tid & 31;

    int seg = w & 1;
    int t0 = tg * 4 + (w >> 1) * 2;
    int slot = dh * 2 + seg;

    float* ws   = sg + w * WARP_SMEM;
    float* s_xl = ws;
    float* bA   = ws + SEG_F;
    float* bB   = ws + 2 * SEG_F;

    size_t dof = (size_t)dh * 1536 + seg * SEG_F;
    const float* xls = xl_g + (size_t)bl * DF + dof;
    const float* xh0 = xh_g + ((size_t)bl * Tt + t0) * DF + dof;
    const float* xh1 = xh0 + DF;

    #pragma unroll
    for (int k = 0; k < 6; k++) {
        int o = (lane + 32 * k) * 4;
        CP16((unsigned)__cvta_generic_to_shared(s_xl + o), xls + o);
        CP16((unsigned)__cvta_generic_to_shared(bA + o), xh0 + o);
    }
    asm volatile("cp.async.commit_group;");
    #pragma unroll
    for (int k = 0; k < 6; k++) {
        int o = (lane + 32 * k) * 4;
        CP16((unsigned)__cvta_generic_to_shared(bB + o), xh1 + o);
    }
    asm volatile("cp.async.commit_group;");

    asm volatile("cp.async.wait_group 1;");
    __syncwarp();
    if (tg == 0 && w < 2)
        gram_task<true>(bA, s_xl, lane, bl, t0, slot);
    else
        gram_task<false>(bA, s_xl, lane, bl, t0, slot);

    asm volatile("cp.async.wait_group 0;");
    __syncwarp();
    gram_task<false>(bB, s_xl, lane, bl, t0 + 1, slot);
}

// ---------------------------------------------------------------------------
// k_score: scores + softmax -> tf32 hi/lo planes of att, layout [t][c] with
// row stride 36. Grid 96 x 256.
// ---------------------------------------------------------------------------
__global__ __launch_bounds__(256) void k_score(
    const float* __restrict__ Wq, const float* __restrict__ bq,
    const float* __restrict__ Wm, const float* __restrict__ bm)
{
    __shared__ float s_G[Tt][12];
    __shared__ float s_mq[Cc][Tt];
    __shared__ float s_XL[3];

    int bl = blockIdx.x;
    int tid = threadIdx.x, w = tid >> 5, lane = tid & 31;

    if (tid < 3)
        s_XL[tid] = g_XL[0][bl][tid] + g_XL[1][bl][tid]
                  + g_XL[2][bl][tid] + g_XL[3][bl][tid];
    for (int i = tid; i < Tt * 12; i += 256)
        ((float*)s_G)[i] = g_G[((size_t)0 * BL + bl) * Tt * 12 + i]
                         + g_G[((size_t)1 * BL + bl) * Tt * 12 + i]
                         + g_G[((size_t)2 * BL + bl) * Tt * 12 + i]
                         + g_G[((size_t)3 * BL + bl) * Tt * 12 + i];
    __syncthreads();

    for (int i = tid; i < Cc * Tt; i += 256) {
        int c = i / Tt, t = i - c * Tt;
        float wm0 = Wm[c * 3 + 0], wm1 = Wm[c * 3 + 1], wm2 = Wm[c * 3 + 2];
        float wq0 = Wq[c * 3 + 0], wq1 = Wq[c * 3 + 1], wq2 = Wq[c * 3 + 2];
        float bmc = bm[c], bqc = bq[c];
        const float* Gp = s_G[t];
        float v = wm0 * (wq0 * Gp[0] + wq1 * Gp[1] + wq2 * Gp[2])
                + wm1 * (wq0 * Gp[3] + wq1 * Gp[4] + wq2 * Gp[5])
                + wm2 * (wq0 * Gp[6] + wq1 * Gp[7] + wq2 * Gp[8])
                + bmc * (wq0 * s_XL[0] + wq1 * s_XL[1] + wq2 * s_XL[2])
                + bqc * (wm0 * Gp[9] + wm1 * Gp[10] + wm2 * Gp[11])
                + (float)Dd * bmc * bqc;
        s_mq[c][t] = fmaxf(v, 0.0f);
    }
    __syncthreads();

    float* ap = g_atts + (size_t)bl * (2 * Tt * 36);

    #pragma unroll
    for (int k = 0; k < 4; k++) {
        int c = w + 8 * k;
        float v0 = s_mq[c][lane];
        float v1 = (lane < Tt - 32) ? s_mq[c][lane + 32] : -3.0e38f;
        float mx = fmaxf(v0, v1);
        #pragma unroll
        for (int o = 16; o; o >>= 1) mx = fmaxf(mx, __shfl_xor_sync(~0u, mx, o));
        float e0 = __expf(v0 - mx);
        float e1 = (lane < Tt - 32) ? __expf(v1 - mx) : 0.0f;
        float s = e0 + e1;
        #pragma unroll
        for (int o = 16; o; o >>= 1) s += __shfl_xor_sync(~0u, s, o);
        float inv = 1.0f / s;

        float a0v = e0 * inv;
        unsigned h0 = tf32_rna(a0v);
        float lo0 = a0v - __uint_as_float(h0);
        ap[lane * 36 + c] = __uint_as_float(h0);
        ap[Tt * 36 + lane * 36 + c] = __uint_as_float(tf32_rna(lo0));
        if (lane < Tt - 32) {
            float a1v = e1 * inv;
            unsigned h1 = tf32_rna(a1v);
            float lo1 = a1v - __uint_as_float(h1);
            ap[(lane + 32) * 36 + c] = __uint_as_float(h1);
            ap[Tt * 36 + (lane + 32) * 36 + c] = __uint_as_float(tf32_rna(lo1));
        }
    }
}

// ---------------------------------------------------------------------------
// k_out: CTA = (bl, 64-d chunk), 256 thr. Tensor-core H-GEMM:
//   H[32, 192] = att[32, 36] @ xh_tile[36, 192]   via m16n8k8 tf32, 3x split.
// Warp w owns n-tiles [w*24, w*24+24), both m-tiles, K padded to 40 via
// zeroed a2/a3 + b1 on the last k-step. B smem stride 196 -> conflict-free
// fragment loads (bank = 4*tig + gid). H overwrites the B region, then the
// fp32 epilogue applies Wc, q, biases. Grid 1536 x 256, smem ~39KB.
// ---------------------------------------------------------------------------
#define SM_B_F    (Tt * BSTR)          // 7056 (>= 32*196 H region)
#define SM_AH_F   (Tt * 36)            // 1296
#define SM_XL_F   NCOL                 // 192
#define OUT_SMEM_F (SM_B_F + 2 * SM_AH_F + SM_XL_F)   // 9840 floats

__global__ __launch_bounds__(256) void k_out(
    const float* __restrict__ xl_g, const float* __restrict__ xh_g,
    const float* __restrict__ Wq, const float* __restrict__ bq,
    const float* __restrict__ Wc, const float* __restrict__ bc,
    float* __restrict__ out)
{
    extern __shared__ float sm[];
    float* s_B   = sm;                          // [36][196]; reused as H [32][196]
    float* s_ahi = sm + SM_B_F;                 // [36][36]
    float* s_alo = sm + SM_B_F + SM_AH_F;       // [36][36]
    float* s_xl  = sm + SM_B_F + 2 * SM_AH_F;   // [192]

    int blk = blockIdx.x;
    int bl = blk / CHUNKS, chunk = blk - bl * CHUNKS;
    int b = bl / Ll, l = bl - b * Ll;
    int tid = threadIdx.x;
    int w = tid >> 5, lane = tid & 31;
    int g = lane >> 2, tig = lane & 3;

    const float* xh_bl  = xh_g + (size_t)bl * Tt * DF + chunk * NCOL;
    const float* att_src = g_atts + (size_t)bl * (2 * Tt * 36);
    const float* xl_src = xl_g + (size_t)bl * DF + chunk * NCOL;

    // ---- stage: B tile rows (48 cp16 each), att hi+lo (648 cp16), xl (48) ----
    #pragma unroll
    for (int rr = 0; rr < 5; rr++) {
        int r = w + rr * 8;
        if (r < Tt) {
            const float* sb = xh_bl + (size_t)r * DF;
            float* db = s_B + r * BSTR;
            CP16((unsigned)__cvta_generic_to_shared(db + lane * 4), sb + lane * 4);
            if (lane < 16) {
                int o2 = (32 + lane) * 4;
                CP16((unsigned)__cvta_generic_to_shared(db + o2), sb + o2);
            }
        }
    }
    {
        // att: 2592 floats = 648 cp16 contiguous into s_ahi (s_alo adjacent)
        CP16((unsigned)__cvta_generic_to_shared(s_ahi + tid * 4), att_src + tid * 4);
        int i2 = tid + 256;
        CP16((unsigned)__cvta_generic_to_shared(s_ahi + i2 * 4), att_src + i2 * 4);
        int i3 = tid + 512;
        if (i3 < 648)
            CP16((unsigned)__cvta_generic_to_shared(s_ahi + i3 * 4), att_src + i3 * 4);
        // xl
        int j = tid - 192;
        if (j >= 0 && j < 48)
            CP16((unsigned)__cvta_generic_to_shared(s_xl + j * 4), xl_src + j * 4);
    }
    asm volatile("cp.async.commit_group;");
    asm volatile("cp.async.wait_group 0;");
    __syncthreads();

    // ---- mma mainloop ----
    float C[2][3][4];
    #pragma unroll
    for (int mt = 0; mt < 2; mt++)
        #pragma unroll
        for (int nt = 0; nt < 3; nt++)
            #pragma unroll
            for (int q = 0; q < 4; q++) C[mt][nt][q] = 0.0f;

    #pragma unroll
    for (int ks = 0; ks < 5; ks++) {
        int kb = ks * 8;
        bool full = (ks < 4);                    // last step: only k 32..35 valid

        unsigned ahi[2][4], alo[2][4];
        #pragma unroll
        for (int mt = 0; mt < 2; mt++) {
            int r0 = (kb + tig) * 36 + mt * 16 + g;
            ahi[mt][0] = __float_as_uint(s_ahi[r0]);
            ahi[mt][1] = __float_as_uint(s_ahi[r0 + 8]);
            alo[mt][0] = __float_as_uint(s_alo[r0]);
            alo[mt][1] = __float_as_uint(s_alo[r0 + 8]);
            if (full) {
                int r2 = r0 + 4 * 36;
                ahi[mt][2] = __float_as_uint(s_ahi[r2]);
                ahi[mt][3] = __float_as_uint(s_ahi[r2 + 8]);
                alo[mt][2] = __float_as_uint(s_alo[r2]);
                alo[mt][3] = __float_as_uint(s_alo[r2 + 8]);
            } else {
                ahi[mt][2] = ahi[mt][3] = 0u;
                alo[mt][2] = alo[mt][3] = 0u;
            }
        }

        #pragma unroll
        for (int nt = 0; nt < 3; nt++) {
            int nb = w * 24 + nt * 8 + g;
            float x0 = s_B[(kb + tig) * BSTR + nb];
            float x1 = full ? s_B[(kb + tig + 4) * BSTR + nb] : 0.0f;
            unsigned bh0 = tf32_rna(x0);
            unsigned bh1 = tf32_rna(x1);
            unsigned bl0 = tf32_rna(x0 - __uint_as_float(bh0));
            unsigned bl1 = tf32_rna(x1 - __uint_as_float(bh1));
            #pragma unroll
            for (int mt = 0; mt < 2; mt++) {
                MMA_TF32(C[mt][nt], ahi[mt], bh0, bh1);
                MMA_TF32(C[mt][nt], ahi[mt], bl0, bl1);
                MMA_TF32(C[mt][nt], alo[mt], bh0, bh1);
            }
        }
    }

    // ---- dump H into the (no longer needed) B region ----
    __syncthreads();
    #pragma unroll
    for (int mt = 0; mt < 2; mt++) {
        #pragma unroll
        for (int nt = 0; nt < 3; nt++) {
            int c = mt * 16 + g;
            int col = w * 24 + nt * 8 + 2 * tig;
            *(float2*)(s_B + c * BSTR + col) =
                make_float2(C[mt][nt][0], C[mt][nt][1]);
            *(float2*)(s_B + (c + 8) * BSTR + col) =
                make_float2(C[mt][nt][2], C[mt][nt][3]);
        }
    }
    __syncthreads();

    // ---- epilogue: out = q + Wc·H + bc ----
    int c = tid >> 3, db = tid & 7;
    float wc0 = Wc[c * 3 + 0], wc1 = Wc[c * 3 + 1], wc2 = Wc[c * 3 + 2];
    float wq0 = Wq[c * 3 + 0], wq1 = Wq[c * 3 + 1], wq2 = Wq[c * 3 + 2];
    float bcc = bc[c], bqc = bq[c];

    float* op = out + (((size_t)b * Cc + c) * Ll + l) * Dd + chunk * DC;
    const float* hrow = s_B + c * BSTR;

    #pragma unroll
    for (int j = 0; j < 8; j++) {
        int d = j * 8 + db;
        float h0 = hrow[d * 3 + 0], h1 = hrow[d * 3 + 1], h2 = hrow[d * 3 + 2];
        float o = fmaf(wc2, h2, fmaf(wc1, h1, fmaf(wc0, h0, bcc)));
        const float* xp = s_xl + d * 3;
        float q = fmaf(wq2, xp[2], fmaf(wq1, xp[1], fmaf(wq0, xp[0], bqc)));
        op[d] = q + o;
    }
}

extern "C" void kernel_launch(void* const* d_in, const int* in_sizes, int n_in,
                              void* d_out, int out_size)
{
    const float* xl = (const float*)d_in[0];
    const float* xh = (const float*)d_in[1];
    const float* Wq = (const float*)d_in[2];
    const float* bq = (const float*)d_in[3];
    const float* Wm = (const float*)d_in[4];
    const float* bm = (const float*)d_in[5];
    const float* Wc = (const float*)d_in[6];
    const float* bc = (const float*)d_in[7];
    float* out = (float*)d_out;

    static int attr_set = 0;
    if (!attr_set) {
        cudaFuncSetAttribute(k_gram, cudaFuncAttributeMaxDynamicSharedMemorySize,
                             4 * WARP_SMEM * 4);
        cudaFuncSetAttribute(k_out, cudaFuncAttributeMaxDynamicSharedMemorySize,
                             OUT_SMEM_F * 4);
        attr_set = 1;
    }

    k_gram<<<dim3(18, BL), 128, 4 * WARP_SMEM * 4>>>(xh, xl);
    k_score<<<BL, 256>>>(Wq, bq, Wm, bm);
    k_out<<<BL * CHUNKS, 256, OUT_SMEM_F * 4>>>(
        xl, xh, Wq, bq, Wc, bc, out);
}